// round 1
// baseline (speedup 1.0000x reference)
#include <cuda_runtime.h>
#include <math.h>

#define BB  16
#define SS  168
#define NN  200
#define HH  128
#define TT  24
#define NHH 4
#define DHH 32

#define EPITCH  169
#define SCPITCH 169

// shared layout (floats)
#define OFF_ET  0
#define OFF_QR  21632              // 128*169
#define OFF_QB  (OFF_QR + 3072)    // 24*128
#define OFF_QT  (OFF_QB + 3072)    // 96*128 (qtilde / ce / gates 24*512)
#define OFF_SC  (OFF_QT + 12288)   // 96*169 (scores/attn; later small bufs)
#define SMEM_FLOATS (OFF_SC + 16224)
#define SMEM_BYTES  (SMEM_FLOATS * 4)   // 225152

__device__ float g_WkT[HH * HH];
__device__ float g_agg[2][BB * NN * HH];
__device__ float g_aggWh[2][BB * NN * 4 * HH];

__global__ void k_prep(const float* __restrict__ Wk) {
    int idx = blockIdx.x * 256 + threadIdx.x;
    if (idx < HH * HH) {
        int j = idx / HH, hd = idx % HH;
        g_WkT[hd * HH + j] = Wk[j * HH + hd];
    }
}

// agg[l][b][n][h] = sum_m adj[n][m] * h_l[b][m][h]
__global__ void k_agg(const float* __restrict__ h0, const float* __restrict__ h1,
                      const float* __restrict__ adj) {
    int bi  = blockIdx.x;
    int l   = bi / (BB * NN);
    int rem = bi % (BB * NN);
    int b = rem / NN, n = rem % NN;
    const float* hsrc = l ? h1 : h0;
    int hh = threadIdx.x;
    float acc = 0.f;
    #pragma unroll 4
    for (int m = 0; m < NN; m++)
        acc += adj[n * NN + m] * hsrc[(b * NN + m) * HH + hh];
    g_agg[l][rem * HH + hh] = acc;
}

// aggWh[l][b][n][c] = agg[l][b][n][:] @ Wh_l[:,c] + b_l[c]
__global__ void k_aggWh(const float* __restrict__ Wh0, const float* __restrict__ bb0,
                        const float* __restrict__ Wh1, const float* __restrict__ bb1) {
    __shared__ float arow[HH];
    int bi  = blockIdx.x;
    int l   = bi / (BB * NN);
    int rem = bi % (BB * NN);
    const float* Wh = l ? Wh1 : Wh0;
    const float* bv = l ? bb1 : bb0;
    int c = threadIdx.x;  // 0..511
    if (c < HH) arow[c] = g_agg[l][rem * HH + c];
    __syncthreads();
    float acc = bv[c];
    #pragma unroll 4
    for (int i = 0; i < HH; i++)
        acc += arow[i] * Wh[i * 4 * HH + c];
    g_aggWh[l][rem * 4 * HH + c] = acc;
}

__device__ __forceinline__ float sigmoidf_(float x) { return 1.f / (1.f + expf(-x)); }

__global__ __launch_bounds__(256, 1)
void k_mega(const float* __restrict__ enc,  const float* __restrict__ c0g,
            const float* __restrict__ h1g,  const float* __restrict__ c1g,
            const float* __restrict__ stepq,
            const float* __restrict__ Wq,   const float* __restrict__ bq,
            const float* __restrict__ Wv,   const float* __restrict__ bv,
            const float* __restrict__ Wo,   const float* __restrict__ bo,
            const float* __restrict__ ctxW, const float* __restrict__ ctxb,
            const float* __restrict__ Wx0,  const float* __restrict__ lng0, const float* __restrict__ lnb0,
            const float* __restrict__ Wx1,  const float* __restrict__ lng1, const float* __restrict__ lnb1,
            const float* __restrict__ outW, const float* __restrict__ outb,
            float* __restrict__ out_pred,   float* __restrict__ out_attn)
{
    extern __shared__ float sm[];
    float* eT   = sm + OFF_ET;   // [j*169 + s]
    float* qr   = sm + OFF_QR;   // [t*128 + i] query rows (kept for 'combined')
    float* qb   = sm + OFF_QB;   // q proj; later ctx
    float* qt   = sm + OFF_QT;   // qtilde [r*128+j]; later ce; later gates [t*512+c]
    float* sc   = sm + OFF_SC;   // scores/attn [r*169+s]
    float* obuf = sc;            // 24*128
    float* comb = sc + 3072;
    float* lnx  = sc + 6144;
    float* x1b  = sc + 9216;
    float* x2b  = sc + 12288;

    const int tid = threadIdx.x;
    const int b = blockIdx.x / NN, n = blockIdx.x % NN;
    const int rowbase = (b * NN + n) * HH;

    // ---- P0: load encoder tile transposed; build query rows ----
    for (int idx = tid; idx < SS * HH; idx += 256) {
        int s = idx >> 7, j = idx & 127;
        eT[j * EPITCH + s] = enc[((size_t)(b * SS + s) * NN + n) * HH + j];
    }
    for (int idx = tid; idx < TT * HH; idx += 256) {
        int t = idx >> 7, i = idx & 127;
        qr[idx] = stepq[t * HH + i] + h1g[rowbase + i];
    }
    __syncthreads();

    const int c128 = tid & 127, rh = tid >> 7;  // rh in {0,1}: rows rh*12..rh*12+11

    // ---- P1: q = qr @ Wq + bq ----
    {
        float acc[12];
        float bqv = bq[c128];
        #pragma unroll
        for (int k = 0; k < 12; k++) acc[k] = bqv;
        const float* qrb = qr + rh * 12 * HH;
        #pragma unroll 4
        for (int i = 0; i < HH; i++) {
            float w = Wq[i * HH + c128];
            #pragma unroll
            for (int k = 0; k < 12; k++) acc[k] += qrb[k * HH + i] * w;
        }
        float* qd = qb + rh * 12 * HH;
        #pragma unroll
        for (int k = 0; k < 12; k++) qd[k * HH + c128] = acc[k];
    }
    __syncthreads();

    // ---- P2: qtilde[r=t*4+h][j] = sum_d WkT[(h*32+d)][j] * q[t][h*32+d] ----
    {
        int j = c128;
        for (int h = 0; h < NHH; h++) {
            float acc[12];
            #pragma unroll
            for (int k = 0; k < 12; k++) acc[k] = 0.f;
            #pragma unroll 4
            for (int d = 0; d < DHH; d++) {
                float w = g_WkT[(h * DHH + d) * HH + j];
                #pragma unroll
                for (int k = 0; k < 12; k++)
                    acc[k] += qb[(rh * 12 + k) * HH + h * DHH + d] * w;
            }
            #pragma unroll
            for (int k = 0; k < 12; k++) {
                int t = rh * 12 + k;
                qt[(t * NHH + h) * HH + j] = acc[k];
            }
        }
    }
    __syncthreads();

    // ---- P3: scores[r][s] = scale * sum_j qt[r][j]*eT[j][s] ----
    {
        const float scale = 0.17677669529663687f;  // 1/sqrt(32)
        for (int task = tid; task < 24 * 42; task += 256) {
            int sg = task % 42, rg = task / 42;
            float acc[4][4];
            #pragma unroll
            for (int k = 0; k < 4; k++)
                #pragma unroll
                for (int m = 0; m < 4; m++) acc[k][m] = 0.f;
            for (int j = 0; j < HH; j++) {
                float ev[4];
                #pragma unroll
                for (int m = 0; m < 4; m++) ev[m] = eT[j * EPITCH + sg + 42 * m];
                #pragma unroll
                for (int k = 0; k < 4; k++) {
                    float qv = qt[(rg * 4 + k) * HH + j];
                    #pragma unroll
                    for (int m = 0; m < 4; m++) acc[k][m] += qv * ev[m];
                }
            }
            #pragma unroll
            for (int k = 0; k < 4; k++)
                #pragma unroll
                for (int m = 0; m < 4; m++)
                    sc[(rg * 4 + k) * SCPITCH + sg + 42 * m] = acc[k][m] * scale;
        }
    }
    __syncthreads();

    // ---- P4: softmax over s, write attn to global + keep in sc ----
    {
        int warp = tid >> 5, lane = tid & 31;
        for (int r = warp; r < 96; r += 8) {
            float v[6];
            float mx = -1e30f;
            #pragma unroll
            for (int u = 0; u < 6; u++) {
                int s = lane + 32 * u;
                v[u] = (s < SS) ? sc[r * SCPITCH + s] : -1e30f;
                mx = fmaxf(mx, v[u]);
            }
            #pragma unroll
            for (int off = 16; off > 0; off >>= 1)
                mx = fmaxf(mx, __shfl_xor_sync(0xffffffffu, mx, off));
            float sum = 0.f;
            #pragma unroll
            for (int u = 0; u < 6; u++) {
                int s = lane + 32 * u;
                if (s < SS) { v[u] = expf(v[u] - mx); sum += v[u]; }
            }
            #pragma unroll
            for (int off = 16; off > 0; off >>= 1)
                sum += __shfl_xor_sync(0xffffffffu, sum, off);
            float inv = 1.f / sum;
            int t = r >> 2, h = r & 3;
            float* gout = out_attn + ((((size_t)b * TT + t) * NHH + h) * NN + n) * SS;
            #pragma unroll
            for (int u = 0; u < 6; u++) {
                int s = lane + 32 * u;
                if (s < SS) {
                    float a = v[u] * inv;
                    sc[r * SCPITCH + s] = a;
                    gout[s] = a;
                }
            }
        }
    }
    __syncthreads();

    // ---- P5: ce[r][j] = sum_s attn[r][s]*eT[j][s]  (overwrites qt) ----
    {
        int j0 = tid & 31, rg = tid >> 5;  // rows rg*12..+11
        float acc[4][12];
        #pragma unroll
        for (int u = 0; u < 4; u++)
            #pragma unroll
            for (int k = 0; k < 12; k++) acc[u][k] = 0.f;
        for (int s = 0; s < SS; s++) {
            float ev[4];
            #pragma unroll
            for (int u = 0; u < 4; u++) ev[u] = eT[(j0 + 32 * u) * EPITCH + s];
            #pragma unroll
            for (int k = 0; k < 12; k++) {
                float a = sc[(rg * 12 + k) * SCPITCH + s];
                #pragma unroll
                for (int u = 0; u < 4; u++) acc[u][k] += a * ev[u];
            }
        }
        #pragma unroll
        for (int u = 0; u < 4; u++)
            #pragma unroll
            for (int k = 0; k < 12; k++)
                qt[(rg * 12 + k) * HH + j0 + 32 * u] = acc[u][k];
    }
    __syncthreads();

    // ---- P6: ctx[t][hd] = sum_j ce[t*4+h][j]*Wv[j][hd] + bv[hd] (into qb) ----
    {
        int h = c128 >> 5;
        float acc[12];
        float bvv = bv[c128];
        #pragma unroll
        for (int k = 0; k < 12; k++) acc[k] = bvv;
        #pragma unroll 4
        for (int j = 0; j < HH; j++) {
            float w = Wv[j * HH + c128];
            #pragma unroll
            for (int k = 0; k < 12; k++)
                acc[k] += qt[((rh * 12 + k) * NHH + h) * HH + j] * w;
        }
        #pragma unroll
        for (int k = 0; k < 12; k++) qb[(rh * 12 + k) * HH + c128] = acc[k];
    }
    __syncthreads();

    // ---- P7: o = ctx @ Wo + bo (into obuf) ----
    {
        float acc[12];
        float bov = bo[c128];
        #pragma unroll
        for (int k = 0; k < 12; k++) acc[k] = bov;
        const float* cb = qb + rh * 12 * HH;
        #pragma unroll 4
        for (int i = 0; i < HH; i++) {
            float w = Wo[i * HH + c128];
            #pragma unroll
            for (int k = 0; k < 12; k++) acc[k] += cb[k * HH + i] * w;
        }
        #pragma unroll
        for (int k = 0; k < 12; k++) obuf[(rh * 12 + k) * HH + c128] = acc[k];
    }
    __syncthreads();

    // ---- P8: combined = [qr | o] @ ctx_W + ctx_b ----
    {
        float acc[12];
        float cbv = ctxb[c128];
        #pragma unroll
        for (int k = 0; k < 12; k++) acc[k] = cbv;
        const float* qrb = qr + rh * 12 * HH;
        const float* ob  = obuf + rh * 12 * HH;
        #pragma unroll 4
        for (int i = 0; i < HH; i++) {
            float w = ctxW[i * HH + c128];
            #pragma unroll
            for (int k = 0; k < 12; k++) acc[k] += qrb[k * HH + i] * w;
        }
        #pragma unroll 4
        for (int i = 0; i < HH; i++) {
            float w = ctxW[(HH + i) * HH + c128];
            #pragma unroll
            for (int k = 0; k < 12; k++) acc[k] += ob[k * HH + i] * w;
        }
        #pragma unroll
        for (int k = 0; k < 12; k++) comb[(rh * 12 + k) * HH + c128] = acc[k];
    }
    __syncthreads();

    // ==== two GraphLSTM layers ====
    for (int layer = 0; layer < 2; layer++) {
        const float* src  = layer ? x1b : comb;
        const float* lg   = layer ? lng1 : lng0;
        const float* lb   = layer ? lnb1 : lnb0;
        const float* Wx   = layer ? Wx1 : Wx0;
        const float* cg   = layer ? c1g : c0g;
        const float* aggW = g_aggWh[layer] + (size_t)(b * NN + n) * 4 * HH;
        float* dst = layer ? x2b : x1b;

        // LN
        {
            int warp = tid >> 5, lane = tid & 31;
            for (int t = warp; t < TT; t += 8) {
                float x[4];
                float s1 = 0.f;
                #pragma unroll
                for (int u = 0; u < 4; u++) { x[u] = src[t * HH + lane + 32 * u]; s1 += x[u]; }
                #pragma unroll
                for (int off = 16; off > 0; off >>= 1) s1 += __shfl_xor_sync(0xffffffffu, s1, off);
                float mean = s1 * (1.f / HH);
                float s2 = 0.f;
                #pragma unroll
                for (int u = 0; u < 4; u++) { float d = x[u] - mean; s2 += d * d; }
                #pragma unroll
                for (int off = 16; off > 0; off >>= 1) s2 += __shfl_xor_sync(0xffffffffu, s2, off);
                float inv = rsqrtf(s2 * (1.f / HH) + 1e-5f);
                #pragma unroll
                for (int u = 0; u < 4; u++) {
                    int i = lane + 32 * u;
                    lnx[t * HH + i] = (x[u] - mean) * inv * lg[i] + lb[i];
                }
            }
        }
        __syncthreads();

        // gates = lnx @ Wx + aggWh   (into qt, pitch 512; 2 cols per thread)
        {
            float acc0[TT], acc1[TT];
            float a0 = aggW[tid], a1 = aggW[tid + 256];
            #pragma unroll
            for (int t = 0; t < TT; t++) { acc0[t] = a0; acc1[t] = a1; }
            #pragma unroll 2
            for (int i = 0; i < HH; i++) {
                float w0 = Wx[i * 512 + tid];
                float w1 = Wx[i * 512 + tid + 256];
                #pragma unroll
                for (int t = 0; t < TT; t++) {
                    float a = lnx[t * HH + i];
                    acc0[t] += a * w0;
                    acc1[t] += a * w1;
                }
            }
            #pragma unroll
            for (int t = 0; t < TT; t++) {
                qt[t * 512 + tid]       = acc0[t];
                qt[t * 512 + tid + 256] = acc1[t];
            }
        }
        __syncthreads();

        // elementwise LSTM cell (+ residual on layer 1)
        for (int idx = tid; idx < TT * HH; idx += 256) {
            int t = idx >> 7, hh = idx & 127;
            float gi = qt[t * 512 + hh];
            float gf = qt[t * 512 + 128 + hh];
            float gg = qt[t * 512 + 256 + hh];
            float go = qt[t * 512 + 384 + hh];
            float cv = cg[rowbase + hh];
            float cn = sigmoidf_(gf) * cv + sigmoidf_(gi) * tanhf(gg);
            float hv = sigmoidf_(go) * tanhf(cn);
            dst[idx] = layer ? (hv + x1b[idx]) : hv;
        }
        __syncthreads();
    }

    // ---- preds = x2 @ out_W + out_b ----
    {
        int warp = tid >> 5, lane = tid & 31;
        float ob0 = outb[0];
        for (int t = warp; t < TT; t += 8) {
            float acc = 0.f;
            #pragma unroll
            for (int u = 0; u < 4; u++)
                acc += x2b[t * HH + lane + 32 * u] * outW[lane + 32 * u];
            #pragma unroll
            for (int off = 16; off > 0; off >>= 1)
                acc += __shfl_xor_sync(0xffffffffu, acc, off);
            if (lane == 0)
                out_pred[((size_t)b * TT + t) * NN + n] = acc + ob0;
        }
    }
}

extern "C" void kernel_launch(void* const* d_in, const int* in_sizes, int n_in,
                              void* d_out, int out_size) {
    const float* enc   = (const float*)d_in[0];
    const float* h0    = (const float*)d_in[1];
    const float* c0    = (const float*)d_in[2];
    const float* h1    = (const float*)d_in[3];
    const float* c1    = (const float*)d_in[4];
    const float* adj   = (const float*)d_in[5];
    const float* stepq = (const float*)d_in[6];
    const float* Wq    = (const float*)d_in[7];
    const float* bq    = (const float*)d_in[8];
    const float* Wk    = (const float*)d_in[9];
    // d_in[10] = bk: softmax-invariant, unused
    const float* Wv    = (const float*)d_in[11];
    const float* bv    = (const float*)d_in[12];
    const float* Wo    = (const float*)d_in[13];
    const float* bo    = (const float*)d_in[14];
    const float* ctxW  = (const float*)d_in[15];
    const float* ctxb  = (const float*)d_in[16];
    const float* Wx0   = (const float*)d_in[17];
    const float* Wh0   = (const float*)d_in[18];
    const float* b0    = (const float*)d_in[19];
    const float* lng0  = (const float*)d_in[20];
    const float* lnb0  = (const float*)d_in[21];
    const float* Wx1   = (const float*)d_in[22];
    const float* Wh1   = (const float*)d_in[23];
    const float* b1    = (const float*)d_in[24];
    const float* lng1  = (const float*)d_in[25];
    const float* lnb1  = (const float*)d_in[26];
    const float* outW  = (const float*)d_in[27];
    const float* outb  = (const float*)d_in[28];

    float* out      = (float*)d_out;
    float* out_pred = out;
    float* out_attn = out + (size_t)BB * TT * NN;

    cudaFuncSetAttribute(k_mega, cudaFuncAttributeMaxDynamicSharedMemorySize, SMEM_BYTES);

    k_prep<<<(HH * HH + 255) / 256, 256>>>(Wk);
    k_agg<<<2 * BB * NN, 128>>>(h0, h1, adj);
    k_aggWh<<<2 * BB * NN, 512>>>(Wh0, b0, Wh1, b1);
    k_mega<<<BB * NN, 256, SMEM_BYTES>>>(enc, c0, h1, c1, stepq,
                                         Wq, bq, Wv, bv, Wo, bo, ctxW, ctxb,
                                         Wx0, lng0, lnb0, Wx1, lng1, lnb1,
                                         outW, outb, out_pred, out_attn);
}

// round 2
// speedup vs baseline: 1.1837x; 1.1837x over previous
#include <cuda_runtime.h>
#include <math.h>

#define BB  16
#define SS  168
#define NN  200
#define HH  128
#define TT  24
#define NHH 4
#define DHH 32

#define EPITCH  172
#define E4      43
#define SCPITCH 172
#define SC4     43

// shared layout (floats)
#define OFF_ET  0
#define OFF_QR  22016              // 128*172
#define OFF_QB  (OFF_QR + 3072)
#define OFF_QT  (OFF_QB + 3072)    // 96*128 (qtilde / ce / gates 24*512)
#define OFF_SC  (OFF_QT + 12288)   // 96*172 scores/attn; later small bufs
#define SMEM_FLOATS (OFF_SC + 16512)
#define SMEM_BYTES  (SMEM_FLOATS * 4)   // 227840

__device__ float g_WkT[HH * HH];
__device__ float g_agg[2][BB * NN * HH];
__device__ float g_aggWh[2][BB * NN * 4 * HH];

__global__ void k_prep(const float* __restrict__ Wk) {
    int idx = blockIdx.x * 256 + threadIdx.x;
    if (idx < HH * HH) {
        int j = idx / HH, hd = idx % HH;
        g_WkT[hd * HH + j] = Wk[j * HH + hd];
    }
}

__global__ void k_agg(const float* __restrict__ h0, const float* __restrict__ h1,
                      const float* __restrict__ adj) {
    int bi  = blockIdx.x;
    int l   = bi / (BB * NN);
    int rem = bi % (BB * NN);
    int b = rem / NN, n = rem % NN;
    const float* hsrc = l ? h1 : h0;
    int hh = threadIdx.x;
    float acc = 0.f;
    #pragma unroll 4
    for (int m = 0; m < NN; m++)
        acc += adj[n * NN + m] * hsrc[(b * NN + m) * HH + hh];
    g_agg[l][rem * HH + hh] = acc;
}

__global__ void k_aggWh(const float* __restrict__ Wh0, const float* __restrict__ bb0,
                        const float* __restrict__ Wh1, const float* __restrict__ bb1) {
    __shared__ float arow[HH];
    int bi  = blockIdx.x;
    int l   = bi / (BB * NN);
    int rem = bi % (BB * NN);
    const float* Wh = l ? Wh1 : Wh0;
    const float* bv = l ? bb1 : bb0;
    int c = threadIdx.x;  // 0..511
    if (c < HH) arow[c] = g_agg[l][rem * HH + c];
    __syncthreads();
    float acc = bv[c];
    #pragma unroll 4
    for (int i = 0; i < HH; i++)
        acc += arow[i] * Wh[i * 4 * HH + c];
    g_aggWh[l][rem * 4 * HH + c] = acc;
}

__device__ __forceinline__ float sigf(float x) {
    return __fdividef(1.f, 1.f + __expf(fminf(-x, 80.f)));
}
__device__ __forceinline__ float tanhfast(float x) {
    float e = __expf(fminf(2.f * x, 80.f));
    return __fdividef(e - 1.f, e + 1.f);
}

__global__ __launch_bounds__(512, 1)
void k_mega(const float* __restrict__ enc,  const float* __restrict__ c0g,
            const float* __restrict__ h1g,  const float* __restrict__ c1g,
            const float* __restrict__ stepq,
            const float* __restrict__ Wq,   const float* __restrict__ bq,
            const float* __restrict__ Wv,   const float* __restrict__ bv,
            const float* __restrict__ Wo,   const float* __restrict__ bo,
            const float* __restrict__ ctxW, const float* __restrict__ ctxb,
            const float* __restrict__ Wx0,  const float* __restrict__ lng0, const float* __restrict__ lnb0,
            const float* __restrict__ Wx1,  const float* __restrict__ lng1, const float* __restrict__ lnb1,
            const float* __restrict__ outW, const float* __restrict__ outb,
            float* __restrict__ out_pred,   float* __restrict__ out_attn)
{
    extern __shared__ float sm[];
    float* eT   = sm + OFF_ET;   // [j*172 + s]
    float* qr   = sm + OFF_QR;   // [t*128 + i]
    float* qb   = sm + OFF_QB;   // q proj; later ctx
    float* qt   = sm + OFF_QT;   // qtilde/ce [r*128+j]; gates [t*512+c]
    float* sc   = sm + OFF_SC;   // scores/attn [r*172+s]
    float* obuf = sc;            // overlays (after attn consumed)
    float* comb = sc + 3072;
    float* lnx  = sc + 6144;
    float* x1b  = sc + 9216;
    float* x2b  = sc + 12288;

    const int tid = threadIdx.x;
    const int b = blockIdx.x / NN, n = blockIdx.x % NN;
    const int rowbase = (b * NN + n) * HH;

    // ---- P0: encoder tile transposed + query rows ----
    for (int idx = tid; idx < SS * HH; idx += 512) {
        int s = idx >> 7, j = idx & 127;
        eT[j * EPITCH + s] = enc[((size_t)(b * SS + s) * NN + n) * HH + j];
    }
    for (int idx = tid; idx < TT * HH; idx += 512) {
        int t = idx >> 7, i = idx & 127;
        qr[idx] = stepq[t * HH + i] + h1g[rowbase + i];
    }
    __syncthreads();

    const int c128 = tid & 127, rh = tid >> 7;  // rh in {0..3}: 6 rows each

    // ---- P1: q = qr @ Wq + bq ----
    {
        float acc[6];
        float bqv = bq[c128];
        #pragma unroll
        for (int k = 0; k < 6; k++) acc[k] = bqv;
        const float4* qr4 = (const float4*)(qr + rh * 6 * HH);
        for (int i0 = 0; i0 < HH; i0 += 4) {
            float w[4];
            #pragma unroll
            for (int u = 0; u < 4; u++) w[u] = Wq[(i0 + u) * HH + c128];
            #pragma unroll
            for (int k = 0; k < 6; k++) {
                float4 a = qr4[k * 32 + (i0 >> 2)];
                acc[k] += a.x * w[0] + a.y * w[1] + a.z * w[2] + a.w * w[3];
            }
        }
        #pragma unroll
        for (int k = 0; k < 6; k++) qb[(rh * 6 + k) * HH + c128] = acc[k];
    }
    __syncthreads();

    // ---- P2: qtilde[t*4+h][j] = sum_d WkT[h*32+d][j] * q[t][h*32+d] ----
    {
        int j = c128;
        #pragma unroll
        for (int h = 0; h < NHH; h++) {
            float acc[6];
            #pragma unroll
            for (int k = 0; k < 6; k++) acc[k] = 0.f;
            for (int d0 = 0; d0 < DHH; d0 += 4) {
                float w[4];
                #pragma unroll
                for (int u = 0; u < 4; u++) w[u] = g_WkT[(h * DHH + d0 + u) * HH + j];
                #pragma unroll
                for (int k = 0; k < 6; k++) {
                    float4 a = *(const float4*)&qb[(rh * 6 + k) * HH + h * DHH + d0];
                    acc[k] += a.x * w[0] + a.y * w[1] + a.z * w[2] + a.w * w[3];
                }
            }
            #pragma unroll
            for (int k = 0; k < 6; k++)
                qt[((rh * 6 + k) * NHH + h) * HH + j] = acc[k];
        }
    }
    __syncthreads();

    // ---- P3: scores[r][s] = scale * sum_j qt[r][j]*eT[j][s] ----
    if (tid < 504) {
        const float scale = 0.17677669529663687f;  // 1/sqrt(32)
        int sg = tid % 42, rg = tid / 42;          // rg<12: 8 rows each
        float acc[8][4];
        #pragma unroll
        for (int k = 0; k < 8; k++)
            #pragma unroll
            for (int m = 0; m < 4; m++) acc[k][m] = 0.f;
        const float4* qt4 = (const float4*)qt;
        for (int j4 = 0; j4 < 32; j4++) {
            float4 qv[8];
            #pragma unroll
            for (int k = 0; k < 8; k++) qv[k] = qt4[(rg * 8 + k) * 32 + j4];
            #pragma unroll
            for (int u = 0; u < 4; u++) {
                float ev[4];
                #pragma unroll
                for (int m = 0; m < 4; m++)
                    ev[m] = eT[(j4 * 4 + u) * EPITCH + sg + 42 * m];
                #pragma unroll
                for (int k = 0; k < 8; k++) {
                    float qs = (u == 0) ? qv[k].x : (u == 1) ? qv[k].y : (u == 2) ? qv[k].z : qv[k].w;
                    #pragma unroll
                    for (int m = 0; m < 4; m++) acc[k][m] += qs * ev[m];
                }
            }
        }
        #pragma unroll
        for (int k = 0; k < 8; k++)
            #pragma unroll
            for (int m = 0; m < 4; m++)
                sc[(rg * 8 + k) * SCPITCH + sg + 42 * m] = acc[k][m] * scale;
    }
    __syncthreads();

    // ---- P4: softmax over s; write attn ----
    {
        int warp = tid >> 5, lane = tid & 31;
        for (int r = warp; r < 96; r += 16) {
            float v[6];
            float mx = -1e30f;
            #pragma unroll
            for (int u = 0; u < 6; u++) {
                int s = lane + 32 * u;
                v[u] = (s < SS) ? sc[r * SCPITCH + s] : -1e30f;
                mx = fmaxf(mx, v[u]);
            }
            #pragma unroll
            for (int off = 16; off > 0; off >>= 1)
                mx = fmaxf(mx, __shfl_xor_sync(0xffffffffu, mx, off));
            float sum = 0.f;
            #pragma unroll
            for (int u = 0; u < 6; u++) {
                int s = lane + 32 * u;
                if (s < SS) { v[u] = __expf(v[u] - mx); sum += v[u]; }
            }
            #pragma unroll
            for (int off = 16; off > 0; off >>= 1)
                sum += __shfl_xor_sync(0xffffffffu, sum, off);
            float inv = __fdividef(1.f, sum);
            int t = r >> 2, h = r & 3;
            float* gout = out_attn + ((((size_t)b * TT + t) * NHH + h) * NN + n) * SS;
            #pragma unroll
            for (int u = 0; u < 6; u++) {
                int s = lane + 32 * u;
                if (s < SS) {
                    float a = v[u] * inv;
                    sc[r * SCPITCH + s] = a;
                    gout[s] = a;
                }
            }
        }
    }
    __syncthreads();

    // ---- P5: ce[r][j] = sum_s attn[r][s]*eT[j][s]  (into qt) ----
    {
        int j0 = tid & 31, rg = tid >> 5;  // rg<16: 6 rows each
        float acc[4][6];
        #pragma unroll
        for (int u = 0; u < 4; u++)
            #pragma unroll
            for (int k = 0; k < 6; k++) acc[u][k] = 0.f;
        const float4* eT4 = (const float4*)eT;
        const float4* sc4 = (const float4*)sc;
        for (int s4 = 0; s4 < 42; s4++) {
            float4 av[6];
            #pragma unroll
            for (int k = 0; k < 6; k++) av[k] = sc4[(rg * 6 + k) * SC4 + s4];
            #pragma unroll
            for (int u = 0; u < 4; u++) {
                float4 ev = eT4[(j0 + 32 * u) * E4 + s4];
                #pragma unroll
                for (int k = 0; k < 6; k++)
                    acc[u][k] += av[k].x * ev.x + av[k].y * ev.y + av[k].z * ev.z + av[k].w * ev.w;
            }
        }
        #pragma unroll
        for (int u = 0; u < 4; u++)
            #pragma unroll
            for (int k = 0; k < 6; k++)
                qt[(rg * 6 + k) * HH + j0 + 32 * u] = acc[u][k];
    }
    __syncthreads();

    // ---- P6: ctx[t][hd] = sum_j ce[t*4+h][j]*Wv[j][hd] + bv (into qb) ----
    {
        int h = c128 >> 5;
        float acc[6];
        float bvv = bv[c128];
        #pragma unroll
        for (int k = 0; k < 6; k++) acc[k] = bvv;
        for (int j0 = 0; j0 < HH; j0 += 4) {
            float w[4];
            #pragma unroll
            for (int u = 0; u < 4; u++) w[u] = Wv[(j0 + u) * HH + c128];
            #pragma unroll
            for (int k = 0; k < 6; k++) {
                float4 a = *(const float4*)&qt[((rh * 6 + k) * NHH + h) * HH + j0];
                acc[k] += a.x * w[0] + a.y * w[1] + a.z * w[2] + a.w * w[3];
            }
        }
        #pragma unroll
        for (int k = 0; k < 6; k++) qb[(rh * 6 + k) * HH + c128] = acc[k];
    }
    __syncthreads();

    // ---- P7: o = ctx @ Wo + bo (into obuf) ----
    {
        float acc[6];
        float bov = bo[c128];
        #pragma unroll
        for (int k = 0; k < 6; k++) acc[k] = bov;
        const float4* cb4 = (const float4*)(qb + rh * 6 * HH);
        for (int i0 = 0; i0 < HH; i0 += 4) {
            float w[4];
            #pragma unroll
            for (int u = 0; u < 4; u++) w[u] = Wo[(i0 + u) * HH + c128];
            #pragma unroll
            for (int k = 0; k < 6; k++) {
                float4 a = cb4[k * 32 + (i0 >> 2)];
                acc[k] += a.x * w[0] + a.y * w[1] + a.z * w[2] + a.w * w[3];
            }
        }
        #pragma unroll
        for (int k = 0; k < 6; k++) obuf[(rh * 6 + k) * HH + c128] = acc[k];
    }
    __syncthreads();

    // ---- P8: combined = [qr | o] @ ctx_W + ctx_b ----
    {
        float acc[6];
        float cbv = ctxb[c128];
        #pragma unroll
        for (int k = 0; k < 6; k++) acc[k] = cbv;
        const float4* qr4 = (const float4*)(qr + rh * 6 * HH);
        const float4* ob4 = (const float4*)(obuf + rh * 6 * HH);
        for (int i0 = 0; i0 < HH; i0 += 4) {
            float w[4];
            #pragma unroll
            for (int u = 0; u < 4; u++) w[u] = ctxW[(i0 + u) * HH + c128];
            #pragma unroll
            for (int k = 0; k < 6; k++) {
                float4 a = qr4[k * 32 + (i0 >> 2)];
                acc[k] += a.x * w[0] + a.y * w[1] + a.z * w[2] + a.w * w[3];
            }
        }
        for (int i0 = 0; i0 < HH; i0 += 4) {
            float w[4];
            #pragma unroll
            for (int u = 0; u < 4; u++) w[u] = ctxW[(HH + i0 + u) * HH + c128];
            #pragma unroll
            for (int k = 0; k < 6; k++) {
                float4 a = ob4[k * 32 + (i0 >> 2)];
                acc[k] += a.x * w[0] + a.y * w[1] + a.z * w[2] + a.w * w[3];
            }
        }
        #pragma unroll
        for (int k = 0; k < 6; k++) comb[(rh * 6 + k) * HH + c128] = acc[k];
    }
    __syncthreads();

    // ==== two GraphLSTM layers ====
    for (int layer = 0; layer < 2; layer++) {
        const float* src  = layer ? x1b : comb;
        const float* lg   = layer ? lng1 : lng0;
        const float* lb   = layer ? lnb1 : lnb0;
        const float* Wx   = layer ? Wx1 : Wx0;
        const float* cg   = layer ? c1g : c0g;
        const float* aggW = g_aggWh[layer] + (size_t)(b * NN + n) * 4 * HH;
        float* dst = layer ? x2b : x1b;

        // LN
        {
            int warp = tid >> 5, lane = tid & 31;
            for (int t = warp; t < TT; t += 16) {
                float x[4];
                float s1 = 0.f;
                #pragma unroll
                for (int u = 0; u < 4; u++) { x[u] = src[t * HH + lane + 32 * u]; s1 += x[u]; }
                #pragma unroll
                for (int off = 16; off > 0; off >>= 1) s1 += __shfl_xor_sync(0xffffffffu, s1, off);
                float mean = s1 * (1.f / HH);
                float s2 = 0.f;
                #pragma unroll
                for (int u = 0; u < 4; u++) { float d = x[u] - mean; s2 += d * d; }
                #pragma unroll
                for (int off = 16; off > 0; off >>= 1) s2 += __shfl_xor_sync(0xffffffffu, s2, off);
                float inv = rsqrtf(s2 * (1.f / HH) + 1e-5f);
                #pragma unroll
                for (int u = 0; u < 4; u++) {
                    int i = lane + 32 * u;
                    lnx[t * HH + i] = (x[u] - mean) * inv * lg[i] + lb[i];
                }
            }
        }
        __syncthreads();

        // gates = lnx @ Wx + aggWh  (into qt, pitch 512)
        {
            int rh2 = tid >> 8, c = tid & 255;  // 12 rows, cols c & c+256
            float acc0[12], acc1[12];
            float a0 = aggW[c], a1 = aggW[c + 256];
            #pragma unroll
            for (int k = 0; k < 12; k++) { acc0[k] = a0; acc1[k] = a1; }
            const float4* ln4 = (const float4*)(lnx + rh2 * 12 * HH);
            for (int i0 = 0; i0 < HH; i0 += 4) {
                float w0[4], w1[4];
                #pragma unroll
                for (int u = 0; u < 4; u++) {
                    w0[u] = Wx[(i0 + u) * 512 + c];
                    w1[u] = Wx[(i0 + u) * 512 + c + 256];
                }
                #pragma unroll
                for (int k = 0; k < 12; k++) {
                    float4 a = ln4[k * 32 + (i0 >> 2)];
                    acc0[k] += a.x * w0[0] + a.y * w0[1] + a.z * w0[2] + a.w * w0[3];
                    acc1[k] += a.x * w1[0] + a.y * w1[1] + a.z * w1[2] + a.w * w1[3];
                }
            }
            #pragma unroll
            for (int k = 0; k < 12; k++) {
                qt[(rh2 * 12 + k) * 512 + c]       = acc0[k];
                qt[(rh2 * 12 + k) * 512 + c + 256] = acc1[k];
            }
        }
        __syncthreads();

        // elementwise LSTM cell (+ residual on layer 1)
        for (int idx = tid; idx < TT * HH; idx += 512) {
            int t = idx >> 7, hh = idx & 127;
            float gi = qt[t * 512 + hh];
            float gf = qt[t * 512 + 128 + hh];
            float gg = qt[t * 512 + 256 + hh];
            float go = qt[t * 512 + 384 + hh];
            float cv = cg[rowbase + hh];
            float cn = sigf(gf) * cv + sigf(gi) * tanhfast(gg);
            float hv = sigf(go) * tanhfast(cn);
            dst[idx] = layer ? (hv + x1b[idx]) : hv;
        }
        __syncthreads();
    }

    // ---- preds = x2 @ out_W + out_b ----
    {
        int warp = tid >> 5, lane = tid & 31;
        float ob0 = outb[0];
        for (int t = warp; t < TT; t += 16) {
            float acc = 0.f;
            #pragma unroll
            for (int u = 0; u < 4; u++)
                acc += x2b[t * HH + lane + 32 * u] * outW[lane + 32 * u];
            #pragma unroll
            for (int off = 16; off > 0; off >>= 1)
                acc += __shfl_xor_sync(0xffffffffu, acc, off);
            if (lane == 0)
                out_pred[((size_t)b * TT + t) * NN + n] = acc + ob0;
        }
    }
}

extern "C" void kernel_launch(void* const* d_in, const int* in_sizes, int n_in,
                              void* d_out, int out_size) {
    const float* enc   = (const float*)d_in[0];
    const float* h0    = (const float*)d_in[1];
    const float* c0    = (const float*)d_in[2];
    const float* h1    = (const float*)d_in[3];
    const float* c1    = (const float*)d_in[4];
    const float* adj   = (const float*)d_in[5];
    const float* stepq = (const float*)d_in[6];
    const float* Wq    = (const float*)d_in[7];
    const float* bq    = (const float*)d_in[8];
    const float* Wk    = (const float*)d_in[9];
    // d_in[10] = bk: softmax-invariant, unused
    const float* Wv    = (const float*)d_in[11];
    const float* bv    = (const float*)d_in[12];
    const float* Wo    = (const float*)d_in[13];
    const float* bo    = (const float*)d_in[14];
    const float* ctxW  = (const float*)d_in[15];
    const float* ctxb  = (const float*)d_in[16];
    const float* Wx0   = (const float*)d_in[17];
    const float* Wh0   = (const float*)d_in[18];
    const float* b0    = (const float*)d_in[19];
    const float* lng0  = (const float*)d_in[20];
    const float* lnb0  = (const float*)d_in[21];
    const float* Wx1   = (const float*)d_in[22];
    const float* Wh1   = (const float*)d_in[23];
    const float* b1    = (const float*)d_in[24];
    const float* lng1  = (const float*)d_in[25];
    const float* lnb1  = (const float*)d_in[26];
    const float* outW  = (const float*)d_in[27];
    const float* outb  = (const float*)d_in[28];

    float* out      = (float*)d_out;
    float* out_pred = out;
    float* out_attn = out + (size_t)BB * TT * NN;

    cudaFuncSetAttribute(k_mega, cudaFuncAttributeMaxDynamicSharedMemorySize, SMEM_BYTES);

    k_prep<<<(HH * HH + 255) / 256, 256>>>(Wk);
    k_agg<<<2 * BB * NN, 128>>>(h0, h1, adj);
    k_aggWh<<<2 * BB * NN, 512>>>(Wh0, b0, Wh1, b1);
    k_mega<<<BB * NN, 512, SMEM_BYTES>>>(enc, c0, h1, c1, stepq,
                                         Wq, bq, Wv, bv, Wo, bo, ctxW, ctxb,
                                         Wx0, lng0, lnb0, Wx1, lng1, lnb1,
                                         outW, outb, out_pred, out_attn);
}

// round 4
// speedup vs baseline: 1.2876x; 1.0878x over previous
#include <cuda_runtime.h>

#define BB  16
#define SS  168
#define NN  200
#define HH  128
#define TT  24
#define NHH 4
#define DHH 32

#define EPITCH  172
#define E4      43
#define SCPITCH 172
#define SC4     43

// shared layout (floats)
#define OFF_ET  0
#define OFF_QR  22016              // 128*172
#define OFF_QB  (OFF_QR + 3072)
#define OFF_QT  (OFF_QB + 3072)    // 96*128 (qtilde / ce / gates 24*512)
#define OFF_SC  (OFF_QT + 12288)   // 96*172 scores/attn; later small bufs; weight stage for P1/P2
#define SMEM_FLOATS (OFF_SC + 16512)
#define SMEM_BYTES  (SMEM_FLOATS * 4)   // 227840

#define AGG_SMEM (NN * HH * 4)     // 102400

__device__ float g_WkT[HH * HH];
__device__ float g_agg[2][BB * NN * HH];
__device__ float g_aggWh[2][BB * NN * 4 * HH];

__global__ void k_prep(const float* __restrict__ Wk) {
    int idx = blockIdx.x * 256 + threadIdx.x;
    if (idx < HH * HH) {
        int j = idx / HH, hd = idx % HH;
        g_WkT[hd * HH + j] = Wk[j * HH + hd];
    }
}

// agg[l][b][n][hh] = sum_m adj[n][m] * h_l[b][m][hh]; one block per (l,b)
__global__ __launch_bounds__(512, 1)
void k_agg(const float* __restrict__ h0, const float* __restrict__ h1,
           const float* __restrict__ adj) {
    extern __shared__ float hS[];  // [200*128]
    int l = blockIdx.x >> 4, b = blockIdx.x & 15;
    const float* hsrc = (l ? h1 : h0) + (size_t)b * NN * HH;
    for (int idx = threadIdx.x; idx < NN * HH; idx += 512) hS[idx] = hsrc[idx];
    __syncthreads();
    int hh = threadIdx.x & 127, g = threadIdx.x >> 7;  // g 0..3
    const float4* adj4 = (const float4*)adj;           // row pitch 50 float4
    for (int c5 = 0; c5 < 5; c5++) {
        int n0 = g * 50 + c5 * 10;
        float acc[10];
        #pragma unroll
        for (int k = 0; k < 10; k++) acc[k] = 0.f;
        for (int m4 = 0; m4 < 50; m4++) {
            float4 av[10];
            #pragma unroll
            for (int k = 0; k < 10; k++) av[k] = adj4[(n0 + k) * 50 + m4];
            #pragma unroll
            for (int u = 0; u < 4; u++) {
                float hv = hS[(m4 * 4 + u) * HH + hh];
                #pragma unroll
                for (int k = 0; k < 10; k++)
                    acc[k] += ((const float*)&av[k])[u] * hv;
            }
        }
        #pragma unroll
        for (int k = 0; k < 10; k++)
            g_agg[l][((size_t)b * NN + n0 + k) * HH + hh] = acc[k];
    }
}

// aggWh[l][b][n][c] = agg[l][b][n][:] @ Wh_l[:,c] + b_l[c]; one block per (l,b)
__global__ __launch_bounds__(512, 1)
void k_aggWh(const float* __restrict__ Wh0, const float* __restrict__ bb0,
             const float* __restrict__ Wh1, const float* __restrict__ bb1) {
    extern __shared__ float aggS[];  // [200*128]
    int l = blockIdx.x >> 4, b = blockIdx.x & 15;
    const float* Wh   = l ? Wh1 : Wh0;
    const float* bias = l ? bb1 : bb0;
    const float* asrc = g_agg[l] + (size_t)b * NN * HH;
    for (int idx = threadIdx.x; idx < NN * HH; idx += 512) aggS[idx] = asrc[idx];
    __syncthreads();
    int c = threadIdx.x;
    float bsv = bias[c];
    const float4* a4 = (const float4*)aggS;  // row pitch 32 float4
    float* dst = g_aggWh[l] + (size_t)b * NN * 4 * HH;
    for (int ch = 0; ch < 4; ch++) {
        int n0 = ch * 50;
        float acc[50];
        #pragma unroll
        for (int k = 0; k < 50; k++) acc[k] = bsv;
        for (int i4 = 0; i4 < 32; i4++) {
            float w0 = Wh[(i4 * 4 + 0) * 512 + c];
            float w1 = Wh[(i4 * 4 + 1) * 512 + c];
            float w2 = Wh[(i4 * 4 + 2) * 512 + c];
            float w3 = Wh[(i4 * 4 + 3) * 512 + c];
            #pragma unroll
            for (int k = 0; k < 50; k++) {
                float4 a = a4[(n0 + k) * 32 + i4];
                acc[k] += a.x * w0 + a.y * w1 + a.z * w2 + a.w * w3;
            }
        }
        #pragma unroll
        for (int k = 0; k < 50; k++) dst[(n0 + k) * 512 + c] = acc[k];
    }
}

__device__ __forceinline__ float sigf(float x) {
    return __fdividef(1.f, 1.f + __expf(fminf(-x, 80.f)));
}
__device__ __forceinline__ float tanhfast(float x) {
    float e = __expf(fminf(2.f * x, 80.f));
    return __fdividef(e - 1.f, e + 1.f);
}

// stage exactly 16384 floats (64KB) into smem, all 512 threads
__device__ __forceinline__ void stage16k(float* __restrict__ dst,
                                         const float* __restrict__ src, int tid) {
    const float4* s4 = (const float4*)src;
    float4* d4 = (float4*)dst;
    #pragma unroll
    for (int i = 0; i < 8; i++) d4[tid + 512 * i] = s4[tid + 512 * i];
}

__global__ __launch_bounds__(512, 1)
void k_mega(const float* __restrict__ enc,  const float* __restrict__ c0g,
            const float* __restrict__ h1g,  const float* __restrict__ c1g,
            const float* __restrict__ stepq,
            const float* __restrict__ Wq,   const float* __restrict__ bq,
            const float* __restrict__ Wv,   const float* __restrict__ bv,
            const float* __restrict__ Wo,   const float* __restrict__ bo,
            const float* __restrict__ ctxW, const float* __restrict__ ctxb,
            const float* __restrict__ Wx0,  const float* __restrict__ lng0, const float* __restrict__ lnb0,
            const float* __restrict__ Wx1,  const float* __restrict__ lng1, const float* __restrict__ lnb1,
            const float* __restrict__ outW, const float* __restrict__ outb,
            float* __restrict__ out_pred,   float* __restrict__ out_attn)
{
    extern __shared__ float sm[];
    float* eT   = sm + OFF_ET;   // [j*172 + s]; later weight stage area
    float* qr   = sm + OFF_QR;   // [t*128 + i]
    float* qb   = sm + OFF_QB;   // q proj; later ctx
    float* qt   = sm + OFF_QT;   // qtilde/ce [r*128+j]; gates [t*512+c]
    float* sc   = sm + OFF_SC;   // P1/P2 weight stage; scores/attn [r*172+s]
    float* obuf = sc;            // overlays after attn consumed
    float* comb = sc + 3072;
    float* lnx  = sc + 6144;
    float* x1b  = sc + 9216;
    float* x2b  = sc + 12288;

    const int tid = threadIdx.x;
    const int b = blockIdx.x / NN, n = blockIdx.x % NN;
    const int rowbase = (b * NN + n) * HH;

    // ---- P0: encoder tile transposed + query rows + stage Wq ----
    for (int idx = tid; idx < SS * HH; idx += 512) {
        int s = idx >> 7, j = idx & 127;
        eT[j * EPITCH + s] = enc[((size_t)(b * SS + s) * NN + n) * HH + j];
    }
    for (int idx = tid; idx < TT * HH; idx += 512) {
        int t = idx >> 7, i = idx & 127;
        qr[idx] = stepq[t * HH + i] + h1g[rowbase + i];
    }
    stage16k(sc, Wq, tid);
    __syncthreads();

    const int c128 = tid & 127, rh = tid >> 7;  // rh 0..3: 6 rows each

    // ---- P1: q = qr @ Wq + bq ----
    {
        float acc[6];
        float bqv = bq[c128];
        #pragma unroll
        for (int k = 0; k < 6; k++) acc[k] = bqv;
        const float4* qr4 = (const float4*)(qr + rh * 6 * HH);
        #pragma unroll 4
        for (int i4 = 0; i4 < 32; i4++) {
            float w0 = sc[(i4 * 4 + 0) * HH + c128];
            float w1 = sc[(i4 * 4 + 1) * HH + c128];
            float w2 = sc[(i4 * 4 + 2) * HH + c128];
            float w3 = sc[(i4 * 4 + 3) * HH + c128];
            #pragma unroll
            for (int k = 0; k < 6; k++) {
                float4 a = qr4[k * 32 + i4];
                acc[k] += a.x * w0 + a.y * w1 + a.z * w2 + a.w * w3;
            }
        }
        #pragma unroll
        for (int k = 0; k < 6; k++) qb[(rh * 6 + k) * HH + c128] = acc[k];
    }
    __syncthreads();

    // ---- P2: qtilde[t*4+h][j] = sum_d WkT[h*32+d][j] * q[t][h*32+d] ----
    stage16k(sc, g_WkT, tid);
    __syncthreads();
    {
        float acc[4][6];
        #pragma unroll
        for (int h = 0; h < 4; h++)
            #pragma unroll
            for (int k = 0; k < 6; k++) acc[h][k] = 0.f;
        const float4* qb4 = (const float4*)(qb + rh * 6 * HH);
        #pragma unroll 4
        for (int c4 = 0; c4 < 32; c4++) {  // c4 = h*8 + d4
            int h = c4 >> 3;
            float w0 = sc[(c4 * 4 + 0) * HH + c128];
            float w1 = sc[(c4 * 4 + 1) * HH + c128];
            float w2 = sc[(c4 * 4 + 2) * HH + c128];
            float w3 = sc[(c4 * 4 + 3) * HH + c128];
            #pragma unroll
            for (int k = 0; k < 6; k++) {
                float4 a = qb4[k * 32 + c4];
                acc[h][k] += a.x * w0 + a.y * w1 + a.z * w2 + a.w * w3;
            }
        }
        #pragma unroll
        for (int h = 0; h < 4; h++)
            #pragma unroll
            for (int k = 0; k < 6; k++)
                qt[((rh * 6 + k) * NHH + h) * HH + c128] = acc[h][k];
    }
    __syncthreads();

    // ---- P3: scores[r][sb*4..+3] — float4 on both operands ----
    if (tid < 504) {
        int sb = tid % 42, rg = tid / 42;  // rg<12: 8 rows each; sb: 4 consecutive s
        float acc[8][4];
        #pragma unroll
        for (int k = 0; k < 8; k++)
            #pragma unroll
            for (int m = 0; m < 4; m++) acc[k][m] = 0.f;
        const float4* qt4 = (const float4*)qt + rg * 8 * 32;
        const float4* eT4 = (const float4*)eT;
        for (int j4 = 0; j4 < 32; j4++) {
            float4 qv[8];
            #pragma unroll
            for (int k = 0; k < 8; k++) qv[k] = qt4[k * 32 + j4];
            #pragma unroll
            for (int u = 0; u < 4; u++) {
                float4 ev = eT4[(j4 * 4 + u) * E4 + sb];
                #pragma unroll
                for (int k = 0; k < 8; k++) {
                    float q = (u == 0) ? qv[k].x : (u == 1) ? qv[k].y : (u == 2) ? qv[k].z : qv[k].w;
                    acc[k][0] += q * ev.x;
                    acc[k][1] += q * ev.y;
                    acc[k][2] += q * ev.z;
                    acc[k][3] += q * ev.w;
                }
            }
        }
        const float scale = 0.17677669529663687f;  // 1/sqrt(32)
        float4* sc4w = (float4*)sc;
        #pragma unroll
        for (int k = 0; k < 8; k++)
            sc4w[(rg * 8 + k) * SC4 + sb] =
                make_float4(acc[k][0] * scale, acc[k][1] * scale, acc[k][2] * scale, acc[k][3] * scale);
    }
    __syncthreads();

    // ---- P4: softmax over s; write attn ----
    {
        int warp = tid >> 5, lane = tid & 31;
        for (int r = warp; r < 96; r += 16) {
            float v[6];
            float mx = -1e30f;
            #pragma unroll
            for (int u = 0; u < 6; u++) {
                int s = lane + 32 * u;
                v[u] = (s < SS) ? sc[r * SCPITCH + s] : -1e30f;
                mx = fmaxf(mx, v[u]);
            }
            #pragma unroll
            for (int off = 16; off > 0; off >>= 1)
                mx = fmaxf(mx, __shfl_xor_sync(0xffffffffu, mx, off));
            float sum = 0.f;
            #pragma unroll
            for (int u = 0; u < 6; u++) {
                int s = lane + 32 * u;
                if (s < SS) { v[u] = __expf(v[u] - mx); sum += v[u]; }
            }
            #pragma unroll
            for (int off = 16; off > 0; off >>= 1)
                sum += __shfl_xor_sync(0xffffffffu, sum, off);
            float inv = __fdividef(1.f, sum);
            int t = r >> 2, h = r & 3;
            float* gout = out_attn + ((((size_t)b * TT + t) * NHH + h) * NN + n) * SS;
            #pragma unroll
            for (int u = 0; u < 6; u++) {
                int s = lane + 32 * u;
                if (s < SS) {
                    float a = v[u] * inv;
                    sc[r * SCPITCH + s] = a;
                    gout[s] = a;
                }
            }
        }
    }
    __syncthreads();

    // ---- P5: ce[r][j] = sum_s attn[r][s]*eT[j][s]  (into qt) ----
    {
        int j0 = tid & 31, rg = tid >> 5;  // rg<16: 6 rows each
        float acc[4][6];
        #pragma unroll
        for (int u = 0; u < 4; u++)
            #pragma unroll
            for (int k = 0; k < 6; k++) acc[u][k] = 0.f;
        const float4* eT4 = (const float4*)eT;
        const float4* sc4 = (const float4*)sc;
        for (int s4 = 0; s4 < 42; s4++) {
            float4 av[6];
            #pragma unroll
            for (int k = 0; k < 6; k++) av[k] = sc4[(rg * 6 + k) * SC4 + s4];
            #pragma unroll
            for (int u = 0; u < 4; u++) {
                float4 ev = eT4[(j0 + 32 * u) * E4 + s4];
                #pragma unroll
                for (int k = 0; k < 6; k++)
                    acc[u][k] += av[k].x * ev.x + av[k].y * ev.y + av[k].z * ev.z + av[k].w * ev.w;
            }
        }
        #pragma unroll
        for (int u = 0; u < 4; u++)
            #pragma unroll
            for (int k = 0; k < 6; k++)
                qt[(rg * 6 + k) * HH + j0 + 32 * u] = acc[u][k];
    }
    __syncthreads();

    // ---- P6: ctx = ce @ Wv(head rows) + bv (into qb); Wv staged in eT ----
    stage16k(eT, Wv, tid);
    __syncthreads();
    {
        int h = c128 >> 5;
        float acc[6];
        float bvv = bv[c128];
        #pragma unroll
        for (int k = 0; k < 6; k++) acc[k] = bvv;
        const float4* ce4 = (const float4*)qt;
        #pragma unroll 4
        for (int j4 = 0; j4 < 32; j4++) {
            float w0 = eT[(j4 * 4 + 0) * HH + c128];
            float w1 = eT[(j4 * 4 + 1) * HH + c128];
            float w2 = eT[(j4 * 4 + 2) * HH + c128];
            float w3 = eT[(j4 * 4 + 3) * HH + c128];
            #pragma unroll
            for (int k = 0; k < 6; k++) {
                float4 a = ce4[((rh * 6 + k) * NHH + h) * 32 + j4];
                acc[k] += a.x * w0 + a.y * w1 + a.z * w2 + a.w * w3;
            }
        }
        #pragma unroll
        for (int k = 0; k < 6; k++) qb[(rh * 6 + k) * HH + c128] = acc[k];
    }
    __syncthreads();

    // ---- P7: o = ctx @ Wo + bo (into obuf); Wo staged in eT ----
    stage16k(eT, Wo, tid);
    __syncthreads();
    {
        float acc[6];
        float bov = bo[c128];
        #pragma unroll
        for (int k = 0; k < 6; k++) acc[k] = bov;
        const float4* cb4 = (const float4*)(qb + rh * 6 * HH);
        #pragma unroll 4
        for (int i4 = 0; i4 < 32; i4++) {
            float w0 = eT[(i4 * 4 + 0) * HH + c128];
            float w1 = eT[(i4 * 4 + 1) * HH + c128];
            float w2 = eT[(i4 * 4 + 2) * HH + c128];
            float w3 = eT[(i4 * 4 + 3) * HH + c128];
            #pragma unroll
            for (int k = 0; k < 6; k++) {
                float4 a = cb4[k * 32 + i4];
                acc[k] += a.x * w0 + a.y * w1 + a.z * w2 + a.w * w3;
            }
        }
        #pragma unroll
        for (int k = 0; k < 6; k++) obuf[(rh * 6 + k) * HH + c128] = acc[k];
    }
    __syncthreads();

    // ---- P8: combined = [qr | o] @ ctx_W + ctx_b; ctxW staged in 2 chunks ----
    {
        float acc[6];
        float cbv = ctxb[c128];
        #pragma unroll
        for (int k = 0; k < 6; k++) acc[k] = cbv;

        stage16k(eT, ctxW, tid);
        __syncthreads();
        const float4* qr4 = (const float4*)(qr + rh * 6 * HH);
        #pragma unroll 4
        for (int i4 = 0; i4 < 32; i4++) {
            float w0 = eT[(i4 * 4 + 0) * HH + c128];
            float w1 = eT[(i4 * 4 + 1) * HH + c128];
            float w2 = eT[(i4 * 4 + 2) * HH + c128];
            float w3 = eT[(i4 * 4 + 3) * HH + c128];
            #pragma unroll
            for (int k = 0; k < 6; k++) {
                float4 a = qr4[k * 32 + i4];
                acc[k] += a.x * w0 + a.y * w1 + a.z * w2 + a.w * w3;
            }
        }
        __syncthreads();
        stage16k(eT, ctxW + HH * HH, tid);
        __syncthreads();
        const float4* ob4 = (const float4*)(obuf + rh * 6 * HH);
        #pragma unroll 4
        for (int i4 = 0; i4 < 32; i4++) {
            float w0 = eT[(i4 * 4 + 0) * HH + c128];
            float w1 = eT[(i4 * 4 + 1) * HH + c128];
            float w2 = eT[(i4 * 4 + 2) * HH + c128];
            float w3 = eT[(i4 * 4 + 3) * HH + c128];
            #pragma unroll
            for (int k = 0; k < 6; k++) {
                float4 a = ob4[k * 32 + i4];
                acc[k] += a.x * w0 + a.y * w1 + a.z * w2 + a.w * w3;
            }
        }
        __syncthreads();
        #pragma unroll
        for (int k = 0; k < 6; k++) comb[(rh * 6 + k) * HH + c128] = acc[k];
    }
    __syncthreads();

    // ==== two GraphLSTM layers ====
    for (int layer = 0; layer < 2; layer++) {
        const float* src  = layer ? x1b : comb;
        const float* lg   = layer ? lng1 : lng0;
        const float* lb   = layer ? lnb1 : lnb0;
        const float* Wx   = layer ? Wx1 : Wx0;
        const float* cg   = layer ? c1g : c0g;
        const float* aggW = g_aggWh[layer] + (size_t)(b * NN + n) * 4 * HH;
        float* dst = layer ? x2b : x1b;

        // LN
        {
            int warp = tid >> 5, lane = tid & 31;
            for (int t = warp; t < TT; t += 16) {
                float x[4];
                float s1 = 0.f;
                #pragma unroll
                for (int u = 0; u < 4; u++) { x[u] = src[t * HH + lane + 32 * u]; s1 += x[u]; }
                #pragma unroll
                for (int off = 16; off > 0; off >>= 1) s1 += __shfl_xor_sync(0xffffffffu, s1, off);
                float mean = s1 * (1.f / HH);
                float s2 = 0.f;
                #pragma unroll
                for (int u = 0; u < 4; u++) { float d = x[u] - mean; s2 += d * d; }
                #pragma unroll
                for (int off = 16; off > 0; off >>= 1) s2 += __shfl_xor_sync(0xffffffffu, s2, off);
                float inv = rsqrtf(s2 * (1.f / HH) + 1e-5f);
                #pragma unroll
                for (int u = 0; u < 4; u++) {
                    int i = lane + 32 * u;
                    lnx[t * HH + i] = (x[u] - mean) * inv * lg[i] + lb[i];
                }
            }
        }
        __syncthreads();

        // gates = lnx @ Wx + aggWh  (into qt, pitch 512); Wx staged in 4 panels
        {
            int rh2 = tid >> 8, c = tid & 255;  // 12 rows each, cols c & c+256
            float acc0[12], acc1[12];
            float a0 = aggW[c], a1 = aggW[c + 256];
            #pragma unroll
            for (int k = 0; k < 12; k++) { acc0[k] = a0; acc1[k] = a1; }
            const float4* ln4 = (const float4*)(lnx + rh2 * 12 * HH);
            for (int p = 0; p < 4; p++) {
                stage16k(eT, Wx + p * 32 * 512, tid);
                __syncthreads();
                #pragma unroll 2
                for (int i4 = 0; i4 < 8; i4++) {  // global i = p*32 + i4*4 + u
                    float w00 = eT[(i4 * 4 + 0) * 512 + c];
                    float w01 = eT[(i4 * 4 + 1) * 512 + c];
                    float w02 = eT[(i4 * 4 + 2) * 512 + c];
                    float w03 = eT[(i4 * 4 + 3) * 512 + c];
                    float w10 = eT[(i4 * 4 + 0) * 512 + c + 256];
                    float w11 = eT[(i4 * 4 + 1) * 512 + c + 256];
                    float w12 = eT[(i4 * 4 + 2) * 512 + c + 256];
                    float w13 = eT[(i4 * 4 + 3) * 512 + c + 256];
                    #pragma unroll
                    for (int k = 0; k < 12; k++) {
                        float4 a = ln4[k * 32 + p * 8 + i4];
                        acc0[k] += a.x * w00 + a.y * w01 + a.z * w02 + a.w * w03;
                        acc1[k] += a.x * w10 + a.y * w11 + a.z * w12 + a.w * w13;
                    }
                }
                __syncthreads();
            }
            #pragma unroll
            for (int k = 0; k < 12; k++) {
                qt[(rh2 * 12 + k) * 512 + c]       = acc0[k];
                qt[(rh2 * 12 + k) * 512 + c + 256] = acc1[k];
            }
        }
        __syncthreads();

        // elementwise LSTM cell (+ residual on layer 1)
        for (int idx = tid; idx < TT * HH; idx += 512) {
            int t = idx >> 7, hh = idx & 127;
            float gi = qt[t * 512 + hh];
            float gf = qt[t * 512 + 128 + hh];
            float gg = qt[t * 512 + 256 + hh];
            float go = qt[t * 512 + 384 + hh];
            float cv = cg[rowbase + hh];
            float cn = sigf(gf) * cv + sigf(gi) * tanhfast(gg);
            float hv = sigf(go) * tanhfast(cn);
            dst[idx] = layer ? (hv + x1b[idx]) : hv;
        }
        __syncthreads();
    }

    // ---- preds = x2 @ out_W + out_b ----
    {
        int warp = tid >> 5, lane = tid & 31;
        float ob0 = outb[0];
        for (int t = warp; t < TT; t += 16) {
            float acc = 0.f;
            #pragma unroll
            for (int u = 0; u < 4; u++)
                acc += x2b[t * HH + lane + 32 * u] * outW[lane + 32 * u];
            #pragma unroll
            for (int off = 16; off > 0; off >>= 1)
                acc += __shfl_xor_sync(0xffffffffu, acc, off);
            if (lane == 0)
                out_pred[((size_t)b * TT + t) * NN + n] = acc + ob0;
        }
    }
}

extern "C" void kernel_launch(void* const* d_in, const int* in_sizes, int n_in,
                              void* d_out, int out_size) {
    const float* enc   = (const float*)d_in[0];
    const float* h0    = (const float*)d_in[1];
    const float* c0    = (const float*)d_in[2];
    const float* h1    = (const float*)d_in[3];
    const float* c1    = (const float*)d_in[4];
    const float* adj   = (const float*)d_in[5];
    const float* stepq = (const float*)d_in[6];
    const float* Wq    = (const float*)d_in[7];
    const float* bq    = (const float*)d_in[8];
    const float* Wk    = (const float*)d_in[9];
    // d_in[10] = bk: softmax-invariant, unused
    const float* Wv    = (const float*)d_in[11];
    const float* bv    = (const float*)d_in[12];
    const float* Wo    = (const float*)d_in[13];
    const float* bo    = (const float*)d_in[14];
    const float* ctxW  = (const float*)d_in[15];
    const float* ctxb  = (const float*)d_in[16];
    const float* Wx0   = (const float*)d_in[17];
    const float* Wh0   = (const float*)d_in[18];
    const float* b0    = (const float*)d_in[19];
    const float* lng0  = (const float*)d_in[20];
    const float* lnb0  = (const float*)d_in[21];
    const float* Wx1   = (const float*)d_in[22];
    const float* Wh1   = (const float*)d_in[23];
    const float* b1    = (const float*)d_in[24];
    const float* lng1  = (const float*)d_in[25];
    const float* lnb1  = (const float*)d_in[26];
    const float* outW  = (const float*)d_in[27];
    const float* outb  = (const float*)d_in[28];

    float* out      = (float*)d_out;
    float* out_pred = out;
    float* out_attn = out + (size_t)BB * TT * NN;

    cudaFuncSetAttribute(k_mega, cudaFuncAttributeMaxDynamicSharedMemorySize, SMEM_BYTES);
    cudaFuncSetAttribute(k_agg, cudaFuncAttributeMaxDynamicSharedMemorySize, AGG_SMEM);
    cudaFuncSetAttribute(k_aggWh, cudaFuncAttributeMaxDynamicSharedMemorySize, AGG_SMEM);

    k_prep<<<(HH * HH + 255) / 256, 256>>>(Wk);
    k_agg<<<2 * BB, 512, AGG_SMEM>>>(h0, h1, adj);
    k_aggWh<<<2 * BB, 512, AGG_SMEM>>>(Wh0, b0, Wh1, b1);
    k_mega<<<BB * NN, 512, SMEM_BYTES>>>(enc, c0, h1, c1, stepq,
                                         Wq, bq, Wv, bv, Wo, bo, ctxW, ctxb,
                                         Wx0, lng0, lnb0, Wx1, lng1, lnb1,
                                         outW, outb, out_pred, out_attn);
}